// round 1
// baseline (speedup 1.0000x reference)
#include <cuda_runtime.h>
#include <math.h>

// Problem constants
#define NSTREAM 4
#define BB      4
#define SSEQ    512
#define EMB     512
#define NHEAD   8
#define HDIM    64
#define MROWS   2048   // BB*SSEQ

// ---------------- scratch (device globals; no cudaMalloc allowed) ------------
__device__ float g_X [4UL*2048*512];   // stacked inputs [s, b*t, e]
__device__ float g_Q [4UL*2048*512];   // [s,b,h,t,d]
__device__ float g_Kb[4UL*2048*512];
__device__ float g_Vb[4UL*2048*512];
__device__ float g_MH[4UL*2048*512];   // attention output, already in the "double transposed" layout
__device__ float g_T1[4UL*2048*512];   // x + attn proj (pre-LN1)
__device__ float g_R1[4UL*2048*512];   // LN1 output
__device__ float g_T2[4UL*2048*512];   // r1 + ffn (pre-LN2)
__device__ float g_HB[4UL*2048*2048];  // FFN hidden

__device__ __forceinline__ float gelu_exact(float x) {
    return 0.5f * x * (1.0f + erff(x * 0.70710678118654752440f));
}

// ---------------- 128x128x16 fp32 GEMM core (8x8 per thread, 256 threads) ----
__device__ __forceinline__ void gemm_tile_128x128(
    const float* __restrict__ A, const float* __restrict__ B,
    int K, int N, int m0, int n0,
    float (&acc)[8][8], float* __restrict__ As, float* __restrict__ Bs)
{
    const int tid = threadIdx.x;
    const int tx = tid & 15, ty = tid >> 4;

    for (int k0 = 0; k0 < K; k0 += 16) {
        __syncthreads();
        // A tile 128x16, stored transposed As[k][m] with pad 132
        #pragma unroll
        for (int p = 0; p < 2; ++p) {
            int ar = (tid >> 2) + p * 64;
            int ak = (tid & 3) << 2;
            float4 a = *(const float4*)(A + (size_t)(m0 + ar) * K + k0 + ak);
            As[(ak + 0) * 132 + ar] = a.x;
            As[(ak + 1) * 132 + ar] = a.y;
            As[(ak + 2) * 132 + ar] = a.z;
            As[(ak + 3) * 132 + ar] = a.w;
        }
        // B tile 16x128, row-major Bs[k][n]
        #pragma unroll
        for (int p = 0; p < 2; ++p) {
            int br = (tid >> 5) + p * 8;
            int bc = (tid & 31) << 2;
            *(float4*)(Bs + br * 128 + bc) =
                *(const float4*)(B + (size_t)(k0 + br) * N + n0 + bc);
        }
        __syncthreads();
        #pragma unroll
        for (int k = 0; k < 16; ++k) {
            float4 a0 = *(const float4*)(As + k * 132 + ty * 8);
            float4 a1 = *(const float4*)(As + k * 132 + ty * 8 + 4);
            float4 b0 = *(const float4*)(Bs + k * 128 + tx * 8);
            float4 b1 = *(const float4*)(Bs + k * 128 + tx * 8 + 4);
            float av[8] = {a0.x, a0.y, a0.z, a0.w, a1.x, a1.y, a1.z, a1.w};
            float bv[8] = {b0.x, b0.y, b0.z, b0.w, b1.x, b1.y, b1.z, b1.w};
            #pragma unroll
            for (int r = 0; r < 8; ++r)
                #pragma unroll
                for (int c = 0; c < 8; ++c)
                    acc[r][c] += av[r] * bv[c];
        }
    }
}

// ---------------- QKV projection: Y = X_s @ W, scattered to [s,b,h,t,d] ------
__global__ __launch_bounds__(256)
void qkv_kernel(const float* __restrict__ Wq, const float* __restrict__ Wk,
                const float* __restrict__ Wv)
{
    __shared__ float As[16 * 132];
    __shared__ float Bs[16 * 128];

    int z = blockIdx.z;
    int s = z / 3, p = z - 3 * s;
    const float* A = g_X + (size_t)s * MROWS * EMB;
    const float* W = (p == 0 ? Wq : (p == 1 ? Wk : Wv)) + (size_t)s * EMB * EMB;
    float* O = (p == 0 ? g_Q : (p == 1 ? g_Kb : g_Vb));

    int m0 = blockIdx.y * 128, n0 = blockIdx.x * 128;
    float acc[8][8] = {};
    gemm_tile_128x128(A, W, EMB, EMB, m0, n0, acc, As, Bs);

    const int tx = threadIdx.x & 15, ty = threadIdx.x >> 4;
    #pragma unroll
    for (int r = 0; r < 8; ++r) {
        int row = m0 + ty * 8 + r;
        int b = row >> 9, t = row & 511;
        #pragma unroll
        for (int cc = 0; cc < 8; cc += 4) {
            int col = n0 + tx * 8 + cc;
            int h = col >> 6, d = col & 63;
            float4 v;
            v.x = acc[r][cc + 0]; v.y = acc[r][cc + 1];
            v.z = acc[r][cc + 2]; v.w = acc[r][cc + 3];
            size_t dst = ((((size_t)s * 4 + b) * 8 + h) * 512 + t) * 64 + d;
            *(float4*)(O + dst) = v;
        }
    }
}

// ---------------- GEMM + epilogue (MODE 0: +bias+resid, MODE 1: +bias,gelu) --
template <int MODE>
__global__ __launch_bounds__(256)
void gemm_ep_kernel(const float* __restrict__ Ab, const float* __restrict__ Bb,
                    const float* __restrict__ biasb, const float* __restrict__ residb,
                    float* __restrict__ Cb, int M, int N, int K)
{
    __shared__ float As[16 * 132];
    __shared__ float Bs[16 * 128];

    int s = blockIdx.z;
    const float* A = Ab + (size_t)s * M * K;
    const float* B = Bb + (size_t)s * K * N;
    const float* bias = biasb + (size_t)s * N;
    float* C = Cb + (size_t)s * M * N;

    int m0 = blockIdx.y * 128, n0 = blockIdx.x * 128;
    float acc[8][8] = {};
    gemm_tile_128x128(A, B, K, N, m0, n0, acc, As, Bs);

    const float* resid = (MODE == 0) ? (residb + (size_t)s * M * N) : nullptr;
    const int tx = threadIdx.x & 15, ty = threadIdx.x >> 4;
    #pragma unroll
    for (int r = 0; r < 8; ++r) {
        int row = m0 + ty * 8 + r;
        #pragma unroll
        for (int cc = 0; cc < 8; cc += 4) {
            int col = n0 + tx * 8 + cc;
            float4 v;
            v.x = acc[r][cc + 0]; v.y = acc[r][cc + 1];
            v.z = acc[r][cc + 2]; v.w = acc[r][cc + 3];
            float4 bsv = *(const float4*)(bias + col);
            v.x += bsv.x; v.y += bsv.y; v.z += bsv.z; v.w += bsv.w;
            if (MODE == 0) {
                float4 rv = *(const float4*)(resid + (size_t)row * N + col);
                v.x += rv.x; v.y += rv.y; v.z += rv.z; v.w += rv.w;
            } else {
                v.x = gelu_exact(v.x); v.y = gelu_exact(v.y);
                v.z = gelu_exact(v.z); v.w = gelu_exact(v.w);
            }
            *(float4*)(C + (size_t)row * N + col) = v;
        }
    }
}

// ---------------- cross-stream flash attention ------------------------------
// out_i = (1/NS) * sum_j softmax( SCALE*inter[i,j] * Q_i K_j^T ) V_j
// One block per (i, b, h, 64-query tile). 256 threads (16x16).
// Output stored pre-transposed: MH[i, b, h*64+d, q]  (exploits S==E reshape quirk).
__global__ __launch_bounds__(256)
void attn_kernel(const float* __restrict__ inter)
{
    __shared__ float Qs[64 * 68];
    __shared__ float Ks[32 * 68];
    __shared__ float Vs[32 * 68];
    __shared__ float Ps[64 * 36];

    const int tid = threadIdx.x;
    const int tx = tid & 15, ty = tid >> 4;
    const int qt = blockIdx.x, h = blockIdx.y, ib = blockIdx.z;
    const int i = ib >> 2, b = ib & 3;

    const float* Qg = g_Q + ((((size_t)i * 4 + b) * 8 + h) * 512 + qt * 64) * 64;
    for (int idx = tid; idx < 64 * 64; idx += 256) {
        int q = idx >> 6, d = idx & 63;
        Qs[q * 68 + d] = Qg[idx];
    }
    float oacc[4][4] = {};

    for (int j = 0; j < 4; ++j) {
        float coef = 0.125f * __ldg(&inter[i * 4 + j]);
        const float* Kg = g_Kb + ((((size_t)j * 4 + b) * 8 + h) * 512) * 64;
        const float* Vg = g_Vb + ((((size_t)j * 4 + b) * 8 + h) * 512) * 64;
        float m[4] = {-1e30f, -1e30f, -1e30f, -1e30f};
        float l[4] = {0.f, 0.f, 0.f, 0.f};
        float jacc[4][4] = {};

        for (int kt = 0; kt < 16; ++kt) {
            __syncthreads();
            for (int idx = tid; idx < 32 * 64; idx += 256) {
                int kk = idx >> 6, d = idx & 63;
                Ks[kk * 68 + d] = Kg[kt * 2048 + idx];
                Vs[kk * 68 + d] = Vg[kt * 2048 + idx];
            }
            __syncthreads();

            // scores: 64q x 32k, each thread 4 rows x 2 cols
            float sc[4][2] = {};
            #pragma unroll
            for (int d = 0; d < 64; d += 4) {
                float4 k0 = *(const float4*)(Ks + (tx * 2 + 0) * 68 + d);
                float4 k1 = *(const float4*)(Ks + (tx * 2 + 1) * 68 + d);
                #pragma unroll
                for (int r = 0; r < 4; ++r) {
                    float4 qv = *(const float4*)(Qs + (ty * 4 + r) * 68 + d);
                    sc[r][0] += qv.x * k0.x + qv.y * k0.y + qv.z * k0.z + qv.w * k0.w;
                    sc[r][1] += qv.x * k1.x + qv.y * k1.y + qv.z * k1.z + qv.w * k1.w;
                }
            }

            // online softmax per row (row group = 16 lanes with same ty)
            #pragma unroll
            for (int r = 0; r < 4; ++r) {
                float s0 = sc[r][0] * coef, s1 = sc[r][1] * coef;
                float mx = fmaxf(s0, s1);
                #pragma unroll
                for (int off = 8; off >= 1; off >>= 1)
                    mx = fmaxf(mx, __shfl_xor_sync(0xffffffffu, mx, off, 16));
                float mn = fmaxf(m[r], mx);
                float alpha = __expf(m[r] - mn);
                float p0 = __expf(s0 - mn);
                float p1 = __expf(s1 - mn);
                Ps[(ty * 4 + r) * 36 + tx * 2 + 0] = p0;
                Ps[(ty * 4 + r) * 36 + tx * 2 + 1] = p1;
                float rs = p0 + p1;
                #pragma unroll
                for (int off = 8; off >= 1; off >>= 1)
                    rs += __shfl_xor_sync(0xffffffffu, rs, off, 16);
                l[r] = l[r] * alpha + rs;
                m[r] = mn;
                jacc[r][0] *= alpha; jacc[r][1] *= alpha;
                jacc[r][2] *= alpha; jacc[r][3] *= alpha;
            }
            __syncthreads();

            // jacc += P @ V  (each thread: 4 rows x 4 d-cols at tx*4)
            #pragma unroll
            for (int kk = 0; kk < 32; kk += 4) {
                float4 v0 = *(const float4*)(Vs + (kk + 0) * 68 + tx * 4);
                float4 v1 = *(const float4*)(Vs + (kk + 1) * 68 + tx * 4);
                float4 v2 = *(const float4*)(Vs + (kk + 2) * 68 + tx * 4);
                float4 v3 = *(const float4*)(Vs + (kk + 3) * 68 + tx * 4);
                #pragma unroll
                for (int r = 0; r < 4; ++r) {
                    float4 pp = *(const float4*)(Ps + (ty * 4 + r) * 36 + kk);
                    jacc[r][0] += pp.x * v0.x + pp.y * v1.x + pp.z * v2.x + pp.w * v3.x;
                    jacc[r][1] += pp.x * v0.y + pp.y * v1.y + pp.z * v2.y + pp.w * v3.y;
                    jacc[r][2] += pp.x * v0.z + pp.y * v1.z + pp.z * v2.z + pp.w * v3.z;
                    jacc[r][3] += pp.x * v0.w + pp.y * v1.w + pp.z * v2.w + pp.w * v3.w;
                }
            }
        }
        #pragma unroll
        for (int r = 0; r < 4; ++r) {
            float inv = 1.0f / l[r];
            oacc[r][0] += jacc[r][0] * inv;
            oacc[r][1] += jacc[r][1] * inv;
            oacc[r][2] += jacc[r][2] * inv;
            oacc[r][3] += jacc[r][3] * inv;
        }
    }

    // transpose through smem, then coalesced store: MH[i,b, h*64+d, qglobal]
    __syncthreads();
    #pragma unroll
    for (int r = 0; r < 4; ++r)
        #pragma unroll
        for (int c = 0; c < 4; ++c)
            Qs[(tx * 4 + c) * 68 + (ty * 4 + r)] = oacc[r][c] * 0.25f;
    __syncthreads();
    float* Og = g_MH + (((size_t)i * 4 + b) * 512 + h * 64) * 512 + qt * 64;
    for (int idx = tid; idx < 64 * 64; idx += 256) {
        int d = idx >> 6, q = idx & 63;
        Og[(size_t)d * 512 + q] = Qs[d * 68 + q];
    }
}

// ---------------- row LayerNorm over E=512 -----------------------------------
__global__ __launch_bounds__(128)
void ln_kernel(const float* __restrict__ in, const float* __restrict__ gw,
               const float* __restrict__ bw, float* __restrict__ out)
{
    int row = blockIdx.x;          // 0..8191 (= s*2048 + b*512 + t)
    int s = row >> 11;
    int t = threadIdx.x;

    float4 xv = ((const float4*)(in + (size_t)row * 512))[t];
    float sum = xv.x + xv.y + xv.z + xv.w;
    float sq  = xv.x * xv.x + xv.y * xv.y + xv.z * xv.z + xv.w * xv.w;
    #pragma unroll
    for (int off = 16; off >= 1; off >>= 1) {
        sum += __shfl_xor_sync(0xffffffffu, sum, off);
        sq  += __shfl_xor_sync(0xffffffffu, sq,  off);
    }
    __shared__ float s_sum[4], s_sq[4];
    int w = t >> 5, lane = t & 31;
    if (lane == 0) { s_sum[w] = sum; s_sq[w] = sq; }
    __syncthreads();
    sum = s_sum[0] + s_sum[1] + s_sum[2] + s_sum[3];
    sq  = s_sq[0]  + s_sq[1]  + s_sq[2]  + s_sq[3];

    float mean = sum * (1.0f / 512.0f);
    float var  = sq  * (1.0f / 512.0f) - mean * mean;
    float inv  = rsqrtf(var + 1e-5f);

    float4 g4 = ((const float4*)(gw + s * 512))[t];
    float4 b4 = ((const float4*)(bw + s * 512))[t];
    float4 o;
    o.x = (xv.x - mean) * inv * g4.x + b4.x;
    o.y = (xv.y - mean) * inv * g4.y + b4.y;
    o.z = (xv.z - mean) * inv * g4.z + b4.z;
    o.w = (xv.w - mean) * inv * g4.w + b4.w;
    ((float4*)(out + (size_t)row * 512))[t] = o;
}

// ---------------- launch -----------------------------------------------------
extern "C" void kernel_launch(void* const* d_in, const int* in_sizes, int n_in,
                              void* d_out, int out_size)
{
    const float* xs[4] = {(const float*)d_in[0], (const float*)d_in[1],
                          (const float*)d_in[2], (const float*)d_in[3]};
    const float* Wq    = (const float*)d_in[4];
    const float* Wk    = (const float*)d_in[5];
    const float* Wv    = (const float*)d_in[6];
    const float* Wo    = (const float*)d_in[7];
    const float* bo    = (const float*)d_in[8];
    const float* ln1g  = (const float*)d_in[9];
    const float* ln1b  = (const float*)d_in[10];
    const float* ln2g  = (const float*)d_in[11];
    const float* ln2b  = (const float*)d_in[12];
    const float* W1    = (const float*)d_in[13];
    const float* bf1   = (const float*)d_in[14];
    const float* W2    = (const float*)d_in[15];
    const float* bf2   = (const float*)d_in[16];
    const float* inter = (const float*)d_in[17];

    float *gX, *gMH, *gT1, *gR1, *gT2, *gHB;
    cudaGetSymbolAddress((void**)&gX,  g_X);
    cudaGetSymbolAddress((void**)&gMH, g_MH);
    cudaGetSymbolAddress((void**)&gT1, g_T1);
    cudaGetSymbolAddress((void**)&gR1, g_R1);
    cudaGetSymbolAddress((void**)&gT2, g_T2);
    cudaGetSymbolAddress((void**)&gHB, g_HB);

    for (int s = 0; s < 4; ++s)
        cudaMemcpyAsync(gX + (size_t)s * MROWS * EMB, xs[s],
                        (size_t)MROWS * EMB * sizeof(float),
                        cudaMemcpyDeviceToDevice);

    // QKV projections: 12 GEMMs of 2048x512x512
    qkv_kernel<<<dim3(4, 16, 12), 256>>>(Wq, Wk, Wv);

    // Cross-stream attention -> MH (pre-transposed layout)
    attn_kernel<<<dim3(8, 8, 16), 256>>>(inter);

    // T1 = MH @ Wo + bo + x
    gemm_ep_kernel<0><<<dim3(4, 16, 4), 256>>>(gMH, Wo, bo, gX, gT1, MROWS, EMB, EMB);

    // R1 = LN1(T1)
    ln_kernel<<<8192, 128>>>(gT1, ln1g, ln1b, gR1);

    // HB = gelu(R1 @ W1 + bf1)
    gemm_ep_kernel<1><<<dim3(16, 16, 4), 256>>>(gR1, W1, bf1, nullptr, gHB, MROWS, 4 * EMB, EMB);

    // T2 = HB @ W2 + bf2 + R1
    gemm_ep_kernel<0><<<dim3(4, 16, 4), 256>>>(gHB, W2, bf2, gR1, gT2, MROWS, EMB, 4 * EMB);

    // out = LN2(T2)
    ln_kernel<<<8192, 128>>>(gT2, ln2g, ln2b, (float*)d_out);
}

// round 2
// speedup vs baseline: 3.1733x; 3.1733x over previous
#include <cuda_runtime.h>
#include <math.h>
#include <stdint.h>

#define MROWS 2048
#define EMB   512

// ---------------- scratch (device globals) -----------------------------------
__device__ float g_X [4UL*2048*512];
__device__ float g_Q [4UL*2048*512];   // [s,b,h,t,d]
__device__ float g_Kb[4UL*2048*512];
__device__ float g_Vb[4UL*2048*512];
__device__ float g_MH[4UL*2048*512];   // attention out, pre-transposed layout
__device__ float g_T1[4UL*2048*512];
__device__ float g_R1[4UL*2048*512];
__device__ float g_T2[4UL*2048*512];
__device__ float g_HB[4UL*2048*2048];

__device__ __forceinline__ float gelu_exact(float x) {
    return 0.5f * x * (1.0f + erff(x * 0.70710678118654752440f));
}
__device__ __forceinline__ uint32_t tf32cvt(float f) {
    uint32_t u; asm("cvt.rna.tf32.f32 %0, %1;" : "=r"(u) : "f"(f)); return u;
}
__device__ __forceinline__ void mma8(float& d0, float& d1, float& d2, float& d3,
    uint32_t a0, uint32_t a1, uint32_t a2, uint32_t a3, uint32_t b0, uint32_t b1) {
    asm volatile("mma.sync.aligned.m16n8k8.row.col.f32.tf32.tf32.f32 "
        "{%0,%1,%2,%3},{%4,%5,%6,%7},{%8,%9},{%0,%1,%2,%3};\n"
        : "+f"(d0), "+f"(d1), "+f"(d2), "+f"(d3)
        : "r"(a0), "r"(a1), "r"(a2), "r"(a3), "r"(b0), "r"(b1));
}
__device__ __forceinline__ void cpa16(float* s, const float* g) {
    uint32_t sa = (uint32_t)__cvta_generic_to_shared(s);
    asm volatile("cp.async.cg.shared.global [%0],[%1],16;\n" :: "r"(sa), "l"(g));
}

// ---------------- tf32 MMA GEMM core: 128x128x32, 256 thr, double-buffered ----
#define AS_LD 36
#define BS_LD 132
#define AS_SZ (128*AS_LD)
#define BS_SZ (32*BS_LD)
#define GEMM_SMEM ((2*AS_SZ + 2*BS_SZ) * sizeof(float))

__device__ __forceinline__ void stage_load(const float* Ag, const float* Bg,
    int K, int N, float* Ad, float* Bd, int tid)
{
    #pragma unroll
    for (int i2 = 0; i2 < 4; ++i2) {
        int idx = tid + (i2 << 8);
        int ar = idx >> 3, ac = (idx & 7) << 2;
        cpa16(Ad + ar * AS_LD + ac, Ag + (size_t)ar * K + ac);
        int bk = idx >> 5, bn = (idx & 31) << 2;
        cpa16(Bd + bk * BS_LD + bn, Bg + (size_t)bk * N + bn);
    }
    asm volatile("cp.async.commit_group;\n" ::: "memory");
}

__device__ __forceinline__ void mma_mainloop(
    const float* __restrict__ A, const float* __restrict__ B,
    int K, int N, int m0, int n0, float (&acc)[4][4][4],
    float* As, float* Bs)
{
    const int tid = threadIdx.x;
    const int lane = tid & 31, warp = tid >> 5;
    const int wm = (warp & 1) * 64, wn = (warp >> 1) * 32;
    const int gg = lane >> 2, rr = lane & 3;
    const int KT = K >> 5;

    stage_load(A + (size_t)m0 * K, B + n0, K, N, As, Bs, tid);

    for (int kt = 0; kt < KT; ++kt) {
        int buf = kt & 1;
        if (kt + 1 < KT) {
            stage_load(A + (size_t)m0 * K + (kt + 1) * 32,
                       B + (size_t)(kt + 1) * 32 * N + n0, K, N,
                       As + (buf ^ 1) * AS_SZ, Bs + (buf ^ 1) * BS_SZ, tid);
            asm volatile("cp.async.wait_group 1;\n" ::: "memory");
        } else {
            asm volatile("cp.async.wait_group 0;\n" ::: "memory");
        }
        __syncthreads();
        const float* Ad = As + buf * AS_SZ;
        const float* Bd = Bs + buf * BS_SZ;
        #pragma unroll
        for (int kk = 0; kk < 4; ++kk) {
            uint32_t af[4][4], bf[4][2];
            int kc = kk * 8 + rr;
            #pragma unroll
            for (int mi = 0; mi < 4; ++mi) {
                int rowb = wm + mi * 16 + gg;
                af[mi][0] = tf32cvt(Ad[rowb * AS_LD + kc]);
                af[mi][1] = tf32cvt(Ad[(rowb + 8) * AS_LD + kc]);
                af[mi][2] = tf32cvt(Ad[rowb * AS_LD + kc + 4]);
                af[mi][3] = tf32cvt(Ad[(rowb + 8) * AS_LD + kc + 4]);
            }
            #pragma unroll
            for (int ni = 0; ni < 4; ++ni) {
                int ncb = wn + ni * 8 + gg;
                bf[ni][0] = tf32cvt(Bd[kc * BS_LD + ncb]);
                bf[ni][1] = tf32cvt(Bd[(kc + 4) * BS_LD + ncb]);
            }
            #pragma unroll
            for (int mi = 0; mi < 4; ++mi)
                #pragma unroll
                for (int ni = 0; ni < 4; ++ni)
                    mma8(acc[mi][ni][0], acc[mi][ni][1], acc[mi][ni][2], acc[mi][ni][3],
                         af[mi][0], af[mi][1], af[mi][2], af[mi][3],
                         bf[ni][0], bf[ni][1]);
        }
        __syncthreads();
    }
}

// ---------------- QKV: X_s @ W -> scatter [s,b,h,t,d] ------------------------
__global__ __launch_bounds__(256)
void qkv_mma(const float* __restrict__ Wq, const float* __restrict__ Wk,
             const float* __restrict__ Wv)
{
    extern __shared__ float sm[];
    float* As = sm; float* Bs = sm + 2 * AS_SZ;
    int z = blockIdx.z; int s = z / 3, p = z - 3 * s;
    const float* A = g_X + (size_t)s * MROWS * EMB;
    const float* W = (p == 0 ? Wq : (p == 1 ? Wk : Wv)) + (size_t)s * EMB * EMB;
    float* O = (p == 0 ? g_Q : (p == 1 ? g_Kb : g_Vb));
    int m0 = blockIdx.y * 128, n0 = blockIdx.x * 128;

    float acc[4][4][4] = {};
    mma_mainloop(A, W, EMB, EMB, m0, n0, acc, As, Bs);

    const int lane = threadIdx.x & 31, warp = threadIdx.x >> 5;
    const int wm = (warp & 1) * 64, wn = (warp >> 1) * 32;
    #pragma unroll
    for (int mi = 0; mi < 4; ++mi) {
        int r0 = m0 + wm + mi * 16 + (lane >> 2);
        #pragma unroll
        for (int ni = 0; ni < 4; ++ni) {
            int c = n0 + wn + ni * 8 + ((lane & 3) << 1);
            int hh = c >> 6, d = c & 63;
            int b0r = r0 >> 9, t0 = r0 & 511;
            size_t dst0 = ((((size_t)s * 4 + b0r) * 8 + hh) * 512 + t0) * 64 + d;
            *(float2*)(O + dst0) = make_float2(acc[mi][ni][0], acc[mi][ni][1]);
            int r1 = r0 + 8; int b1r = r1 >> 9, t1 = r1 & 511;
            size_t dst1 = ((((size_t)s * 4 + b1r) * 8 + hh) * 512 + t1) * 64 + d;
            *(float2*)(O + dst1) = make_float2(acc[mi][ni][2], acc[mi][ni][3]);
        }
    }
}

// ---------------- GEMM + epilogue (MODE 0: bias+resid, MODE 1: bias+gelu) ----
template <int MODE>
__global__ __launch_bounds__(256)
void mma_gemm_ep(const float* __restrict__ Ab, const float* __restrict__ Bb,
                 const float* __restrict__ biasb, const float* __restrict__ residb,
                 float* __restrict__ Cb, int M, int N, int K)
{
    extern __shared__ float sm[];
    float* As = sm; float* Bs = sm + 2 * AS_SZ;
    int s = blockIdx.z;
    const float* A = Ab + (size_t)s * M * K;
    const float* B = Bb + (size_t)s * K * N;
    const float* bias = biasb + (size_t)s * N;
    float* C = Cb + (size_t)s * M * N;
    int m0 = blockIdx.y * 128, n0 = blockIdx.x * 128;

    float acc[4][4][4] = {};
    mma_mainloop(A, B, K, N, m0, n0, acc, As, Bs);

    const float* resid = (MODE == 0) ? (residb + (size_t)s * M * N) : nullptr;
    const int lane = threadIdx.x & 31, warp = threadIdx.x >> 5;
    const int wm = (warp & 1) * 64, wn = (warp >> 1) * 32;
    #pragma unroll
    for (int mi = 0; mi < 4; ++mi) {
        int r0 = m0 + wm + mi * 16 + (lane >> 2);
        #pragma unroll
        for (int ni = 0; ni < 4; ++ni) {
            int c = n0 + wn + ni * 8 + ((lane & 3) << 1);
            float bx = bias[c], by = bias[c + 1];
            #pragma unroll
            for (int hr = 0; hr < 2; ++hr) {
                int rw = r0 + hr * 8;
                float v0 = acc[mi][ni][hr * 2 + 0] + bx;
                float v1 = acc[mi][ni][hr * 2 + 1] + by;
                if (MODE == 0) {
                    float2 rv = *(const float2*)(resid + (size_t)rw * N + c);
                    v0 += rv.x; v1 += rv.y;
                } else {
                    v0 = gelu_exact(v0); v1 = gelu_exact(v1);
                }
                *(float2*)(C + (size_t)rw * N + c) = make_float2(v0, v1);
            }
        }
    }
}

// ---------------- cross-stream flash attention (tf32 mma) --------------------
// block: (qt 64 rows, h, i*4+b); 128 threads = 4 warps, each warp 16 q rows.
#define ATTN_SMEM (4 * 64 * 68 * sizeof(float))
__global__ __launch_bounds__(128)
void attn_mma(const float* __restrict__ inter)
{
    extern __shared__ float sm[];
    float* Qs = sm;              // [64][68]
    float* Ks = Qs + 64 * 68;    // [64][68]
    float* Vs = Ks + 64 * 68;    // [64][68]
    float* Ps = Vs + 64 * 68;    // [64][68]

    const int tid = threadIdx.x, lane = tid & 31, warp = tid >> 5;
    const int qt = blockIdx.x, h = blockIdx.y, ib = blockIdx.z;
    const int i = ib >> 2, b = ib & 3;
    const int gg = lane >> 2, rr = lane & 3;
    const int lq = warp * 16 + gg;           // fragment rows lq, lq+8

    const float* Qg = g_Q + ((((size_t)i * 4 + b) * 8 + h) * 512 + qt * 64) * 64;
    #pragma unroll
    for (int it = 0; it < 8; ++it) {
        int idx = tid + it * 128;
        int q = idx >> 4, d4 = (idx & 15) << 2;
        *(float4*)(Qs + q * 68 + d4) = *(const float4*)(Qg + q * 64 + d4);
    }
    __syncthreads();
    uint32_t qf[8][4];
    #pragma unroll
    for (int kf = 0; kf < 8; ++kf) {
        int c = kf * 8 + rr;
        qf[kf][0] = tf32cvt(Qs[lq * 68 + c]);
        qf[kf][1] = tf32cvt(Qs[(lq + 8) * 68 + c]);
        qf[kf][2] = tf32cvt(Qs[lq * 68 + c + 4]);
        qf[kf][3] = tf32cvt(Qs[(lq + 8) * 68 + c + 4]);
    }

    float Of[8][4] = {};
    for (int j = 0; j < 4; ++j) {
        float coef = 0.125f * __ldg(inter + i * 4 + j);
        const float* Kg = g_Kb + (((size_t)j * 4 + b) * 8 + h) * 512 * 64;
        const float* Vg = g_Vb + (((size_t)j * 4 + b) * 8 + h) * 512 * 64;
        float m0v = -1e30f, m1v = -1e30f, l0 = 0.f, l1 = 0.f;
        float Oj[8][4] = {};

        for (int kt = 0; kt < 8; ++kt) {
            __syncthreads();
            #pragma unroll
            for (int it = 0; it < 8; ++it) {
                int idx = tid + it * 128;
                int kr = idx >> 4, d4 = (idx & 15) << 2;
                *(float4*)(Ks + kr * 68 + d4) =
                    *(const float4*)(Kg + (size_t)(kt * 64 + kr) * 64 + d4);
                *(float4*)(Vs + kr * 68 + d4) =
                    *(const float4*)(Vg + (size_t)(kt * 64 + kr) * 64 + d4);
            }
            __syncthreads();

            // scores S = Q K^T
            float S[8][4] = {};
            #pragma unroll
            for (int kf = 0; kf < 8; ++kf) {
                int kc = kf * 8 + rr;
                #pragma unroll
                for (int nf = 0; nf < 8; ++nf) {
                    int kn = nf * 8 + gg;
                    uint32_t b0 = tf32cvt(Ks[kn * 68 + kc]);
                    uint32_t b1 = tf32cvt(Ks[kn * 68 + kc + 4]);
                    mma8(S[nf][0], S[nf][1], S[nf][2], S[nf][3],
                         qf[kf][0], qf[kf][1], qf[kf][2], qf[kf][3], b0, b1);
                }
            }

            // online softmax (rows lq via c0/c1, lq+8 via c2/c3)
            float mxA = -1e30f, mxB = -1e30f;
            #pragma unroll
            for (int nf = 0; nf < 8; ++nf) {
                S[nf][0] *= coef; S[nf][1] *= coef;
                S[nf][2] *= coef; S[nf][3] *= coef;
                mxA = fmaxf(mxA, fmaxf(S[nf][0], S[nf][1]));
                mxB = fmaxf(mxB, fmaxf(S[nf][2], S[nf][3]));
            }
            mxA = fmaxf(mxA, __shfl_xor_sync(0xffffffffu, mxA, 1));
            mxA = fmaxf(mxA, __shfl_xor_sync(0xffffffffu, mxA, 2));
            mxB = fmaxf(mxB, __shfl_xor_sync(0xffffffffu, mxB, 1));
            mxB = fmaxf(mxB, __shfl_xor_sync(0xffffffffu, mxB, 2));
            float nm0 = fmaxf(m0v, mxA), nm1 = fmaxf(m1v, mxB);
            float al0 = __expf(m0v - nm0), al1 = __expf(m1v - nm1);
            float rs0 = 0.f, rs1 = 0.f;
            #pragma unroll
            for (int nf = 0; nf < 8; ++nf) {
                float p0 = __expf(S[nf][0] - nm0), p1 = __expf(S[nf][1] - nm0);
                float p2 = __expf(S[nf][2] - nm1), p3 = __expf(S[nf][3] - nm1);
                rs0 += p0 + p1; rs1 += p2 + p3;
                int col = nf * 8 + (rr << 1);
                *(float2*)(Ps + lq * 68 + col) = make_float2(p0, p1);
                *(float2*)(Ps + (lq + 8) * 68 + col) = make_float2(p2, p3);
            }
            rs0 += __shfl_xor_sync(0xffffffffu, rs0, 1);
            rs0 += __shfl_xor_sync(0xffffffffu, rs0, 2);
            rs1 += __shfl_xor_sync(0xffffffffu, rs1, 1);
            rs1 += __shfl_xor_sync(0xffffffffu, rs1, 2);
            l0 = l0 * al0 + rs0; l1 = l1 * al1 + rs1;
            m0v = nm0; m1v = nm1;
            #pragma unroll
            for (int nf = 0; nf < 8; ++nf) {
                Oj[nf][0] *= al0; Oj[nf][1] *= al0;
                Oj[nf][2] *= al1; Oj[nf][3] *= al1;
            }
            __syncwarp();

            // Oj += P @ V
            #pragma unroll
            for (int kf = 0; kf < 8; ++kf) {
                int kc = kf * 8 + rr;
                uint32_t pa0 = tf32cvt(Ps[lq * 68 + kc]);
                uint32_t pa1 = tf32cvt(Ps[(lq + 8) * 68 + kc]);
                uint32_t pa2 = tf32cvt(Ps[lq * 68 + kc + 4]);
                uint32_t pa3 = tf32cvt(Ps[(lq + 8) * 68 + kc + 4]);
                #pragma unroll
                for (int nf = 0; nf < 8; ++nf) {
                    int nc = nf * 8 + gg;
                    uint32_t b0 = tf32cvt(Vs[(kf * 8 + rr) * 68 + nc]);
                    uint32_t b1 = tf32cvt(Vs[(kf * 8 + rr + 4) * 68 + nc]);
                    mma8(Oj[nf][0], Oj[nf][1], Oj[nf][2], Oj[nf][3],
                         pa0, pa1, pa2, pa3, b0, b1);
                }
            }
            __syncwarp();
        }
        float inv0 = 1.f / l0, inv1 = 1.f / l1;
        #pragma unroll
        for (int nf = 0; nf < 8; ++nf) {
            Of[nf][0] += Oj[nf][0] * inv0; Of[nf][1] += Oj[nf][1] * inv0;
            Of[nf][2] += Oj[nf][2] * inv1; Of[nf][3] += Oj[nf][3] * inv1;
        }
    }

    // transpose via smem (reuse Ks), then coalesced store to g_MH[i,b,h*64+d, q]
    __syncthreads();
    #pragma unroll
    for (int nf = 0; nf < 8; ++nf) {
        int col = nf * 8 + (rr << 1);
        Ks[col * 68 + lq]           = Of[nf][0] * 0.25f;
        Ks[(col + 1) * 68 + lq]     = Of[nf][1] * 0.25f;
        Ks[col * 68 + lq + 8]       = Of[nf][2] * 0.25f;
        Ks[(col + 1) * 68 + lq + 8] = Of[nf][3] * 0.25f;
    }
    __syncthreads();
    float* Og = g_MH + (((size_t)i * 4 + b) * 512 + h * 64) * 512 + qt * 64;
    #pragma unroll
    for (int it = 0; it < 8; ++it) {
        int idx = tid + it * 128;
        int d = idx >> 4, q4 = (idx & 15) << 2;
        *(float4*)(Og + (size_t)d * 512 + q4) = *(const float4*)(Ks + d * 68 + q4);
    }
}

// ---------------- row LayerNorm over E=512 -----------------------------------
__global__ __launch_bounds__(128)
void ln_kernel(const float* __restrict__ in, const float* __restrict__ gw,
               const float* __restrict__ bw, float* __restrict__ out)
{
    int row = blockIdx.x;
    int s = row >> 11;
    int t = threadIdx.x;

    float4 xv = ((const float4*)(in + (size_t)row * 512))[t];
    float sum = xv.x + xv.y + xv.z + xv.w;
    float sq  = xv.x * xv.x + xv.y * xv.y + xv.z * xv.z + xv.w * xv.w;
    #pragma unroll
    for (int off = 16; off >= 1; off >>= 1) {
        sum += __shfl_xor_sync(0xffffffffu, sum, off);
        sq  += __shfl_xor_sync(0xffffffffu, sq,  off);
    }
    __shared__ float s_sum[4], s_sq[4];
    int w = t >> 5, lane = t & 31;
    if (lane == 0) { s_sum[w] = sum; s_sq[w] = sq; }
    __syncthreads();
    sum = s_sum[0] + s_sum[1] + s_sum[2] + s_sum[3];
    sq  = s_sq[0]  + s_sq[1]  + s_sq[2]  + s_sq[3];

    float mean = sum * (1.0f / 512.0f);
    float var  = sq  * (1.0f / 512.0f) - mean * mean;
    float inv  = rsqrtf(var + 1e-5f);

    float4 g4 = ((const float4*)(gw + s * 512))[t];
    float4 b4 = ((const float4*)(bw + s * 512))[t];
    float4 o;
    o.x = (xv.x - mean) * inv * g4.x + b4.x;
    o.y = (xv.y - mean) * inv * g4.y + b4.y;
    o.z = (xv.z - mean) * inv * g4.z + b4.z;
    o.w = (xv.w - mean) * inv * g4.w + b4.w;
    ((float4*)(out + (size_t)row * 512))[t] = o;
}

// ---------------- launch -----------------------------------------------------
extern "C" void kernel_launch(void* const* d_in, const int* in_sizes, int n_in,
                              void* d_out, int out_size)
{
    const float* xs[4] = {(const float*)d_in[0], (const float*)d_in[1],
                          (const float*)d_in[2], (const float*)d_in[3]};
    const float* Wq    = (const float*)d_in[4];
    const float* Wk    = (const float*)d_in[5];
    const float* Wv    = (const float*)d_in[6];
    const float* Wo    = (const float*)d_in[7];
    const float* bo    = (const float*)d_in[8];
    const float* ln1g  = (const float*)d_in[9];
    const float* ln1b  = (const float*)d_in[10];
    const float* ln2g  = (const float*)d_in[11];
    const float* ln2b  = (const float*)d_in[12];
    const float* W1    = (const float*)d_in[13];
    const float* bf1   = (const float*)d_in[14];
    const float* W2    = (const float*)d_in[15];
    const float* bf2   = (const float*)d_in[16];
    const float* inter = (const float*)d_in[17];

    float *gX, *gMH, *gT1, *gR1, *gT2, *gHB;
    cudaGetSymbolAddress((void**)&gX,  g_X);
    cudaGetSymbolAddress((void**)&gMH, g_MH);
    cudaGetSymbolAddress((void**)&gT1, g_T1);
    cudaGetSymbolAddress((void**)&gR1, g_R1);
    cudaGetSymbolAddress((void**)&gT2, g_T2);
    cudaGetSymbolAddress((void**)&gHB, g_HB);

    cudaFuncSetAttribute(qkv_mma, cudaFuncAttributeMaxDynamicSharedMemorySize, GEMM_SMEM);
    cudaFuncSetAttribute(mma_gemm_ep<0>, cudaFuncAttributeMaxDynamicSharedMemorySize, GEMM_SMEM);
    cudaFuncSetAttribute(mma_gemm_ep<1>, cudaFuncAttributeMaxDynamicSharedMemorySize, GEMM_SMEM);
    cudaFuncSetAttribute(attn_mma, cudaFuncAttributeMaxDynamicSharedMemorySize, ATTN_SMEM);

    for (int s = 0; s < 4; ++s)
        cudaMemcpyAsync(gX + (size_t)s * MROWS * EMB, xs[s],
                        (size_t)MROWS * EMB * sizeof(float),
                        cudaMemcpyDeviceToDevice);

    // QKV projections
    qkv_mma<<<dim3(4, 16, 12), 256, GEMM_SMEM>>>(Wq, Wk, Wv);

    // cross-stream attention
    attn_mma<<<dim3(8, 8, 16), 128, ATTN_SMEM>>>(inter);

    // T1 = MH @ Wo + bo + x
    mma_gemm_ep<0><<<dim3(4, 16, 4), 256, GEMM_SMEM>>>(gMH, Wo, bo, gX, gT1,
                                                       MROWS, EMB, EMB);
    // R1 = LN1(T1)
    ln_kernel<<<8192, 128>>>(gT1, ln1g, ln1b, gR1);

    // HB = gelu(R1 @ W1 + bf1)
    mma_gemm_ep<1><<<dim3(16, 16, 4), 256, GEMM_SMEM>>>(gR1, W1, bf1, nullptr, gHB,
                                                        MROWS, 4 * EMB, EMB);
    // T2 = HB @ W2 + bf2 + R1
    mma_gemm_ep<0><<<dim3(4, 16, 4), 256, GEMM_SMEM>>>(gHB, W2, bf2, gR1, gT2,
                                                       MROWS, EMB, 4 * EMB);
    // out = LN2(T2)
    ln_kernel<<<8192, 128>>>(gT2, ln2g, ln2b, (float*)d_out);
}

// round 3
// speedup vs baseline: 6.4771x; 2.0411x over previous
#include <cuda_runtime.h>
#include <cuda_fp16.h>
#include <math.h>
#include <stdint.h>

#define MROWS 2048
#define EMB   512

// ---------------- scratch (device globals) -----------------------------------
__device__ float  g_T1 [4UL*2048*512];
__device__ float  g_R1 [4UL*2048*512];
__device__ float  g_T2 [4UL*2048*512];
__device__ __half g_Xh [4UL*2048*512];
__device__ __half g_Q  [4UL*2048*512];   // [s,b,h,t,d]
__device__ __half g_K  [4UL*2048*512];
__device__ __half g_V  [4UL*2048*512];
__device__ __half g_MH [4UL*2048*512];   // pre-transposed attention out
__device__ __half g_R1h[4UL*2048*512];
__device__ __half g_HB [4UL*2048*2048];
__device__ __half g_Wqh[4UL*512*512];
__device__ __half g_Wkh[4UL*512*512];
__device__ __half g_Wvh[4UL*512*512];
__device__ __half g_Woh[4UL*512*512];
__device__ __half g_W1h[4UL*512*2048];
__device__ __half g_W2h[4UL*2048*512];

struct R4 { const float* p[4]; };

__device__ __forceinline__ float gelu_exact(float x) {
    return 0.5f * x * (1.0f + erff(x * 0.70710678118654752440f));
}
__device__ __forceinline__ uint32_t sptr(const void* p) {
    return (uint32_t)__cvta_generic_to_shared(p);
}
__device__ __forceinline__ void cpa16(void* s, const void* g) {
    asm volatile("cp.async.cg.shared.global [%0],[%1],16;\n" :: "r"(sptr(s)), "l"(g));
}
__device__ __forceinline__ void ldsm4(uint32_t& r0, uint32_t& r1, uint32_t& r2,
                                      uint32_t& r3, uint32_t a) {
    asm volatile("ldmatrix.sync.aligned.m8n8.x4.shared.b16 {%0,%1,%2,%3},[%4];\n"
        : "=r"(r0), "=r"(r1), "=r"(r2), "=r"(r3) : "r"(a));
}
__device__ __forceinline__ void ldsm4t(uint32_t& r0, uint32_t& r1, uint32_t& r2,
                                       uint32_t& r3, uint32_t a) {
    asm volatile("ldmatrix.sync.aligned.m8n8.x4.trans.shared.b16 {%0,%1,%2,%3},[%4];\n"
        : "=r"(r0), "=r"(r1), "=r"(r2), "=r"(r3) : "r"(a));
}
__device__ __forceinline__ void mmaf16(float& d0, float& d1, float& d2, float& d3,
    uint32_t a0, uint32_t a1, uint32_t a2, uint32_t a3, uint32_t b0, uint32_t b1) {
    asm volatile("mma.sync.aligned.m16n8k16.row.col.f32.f16.f16.f32 "
        "{%0,%1,%2,%3},{%4,%5,%6,%7},{%8,%9},{%0,%1,%2,%3};\n"
        : "+f"(d0), "+f"(d1), "+f"(d2), "+f"(d3)
        : "r"(a0), "r"(a1), "r"(a2), "r"(a3), "r"(b0), "r"(b1));
}
__device__ __forceinline__ uint32_t packh2(float x, float y) {
    __half2 h = __floats2half2_rn(x, y);
    return *(uint32_t*)&h;
}

// ---------------- fp32->fp16 converters ---------------------------------------
__global__ __launch_bounds__(256)
void cvt_kernel(const float* __restrict__ s, __half* __restrict__ d) {
    int i = (blockIdx.x * 256 + threadIdx.x) * 4;
    float4 v = *(const float4*)(s + i);
    *(__half2*)(d + i)     = __floats2half2_rn(v.x, v.y);
    *(__half2*)(d + i + 2) = __floats2half2_rn(v.z, v.w);
}
__global__ __launch_bounds__(256)
void xcvt_kernel(const float* __restrict__ x0, const float* __restrict__ x1,
                 const float* __restrict__ x2, const float* __restrict__ x3) {
    int s = blockIdx.y;
    const float* x = s == 0 ? x0 : s == 1 ? x1 : s == 2 ? x2 : x3;
    int i = (blockIdx.x * 256 + threadIdx.x) * 4;
    float4 v = *(const float4*)(x + i);
    __half* d = g_Xh + (size_t)s * MROWS * EMB + i;
    *(__half2*)(d)     = __floats2half2_rn(v.x, v.y);
    *(__half2*)(d + 2) = __floats2half2_rn(v.z, v.w);
}

// ---------------- fp16 MMA GEMM core: 128x128x32, 256 thr ---------------------
#define LDA 40
#define LDB 152
#define AS_SZ (128*LDA)
#define BS_SZ (32*LDB)

__device__ __forceinline__ void stage_h(const __half* Ag, const __half* Bg,
    int K, int N, __half* Ad, __half* Bd, int tid)
{
    #pragma unroll
    for (int i = 0; i < 2; ++i) {
        int c = tid + (i << 8);
        int ar = c >> 2, ac = (c & 3) << 3;
        cpa16(Ad + ar * LDA + ac, Ag + (size_t)ar * K + ac);
        int br = c >> 4, bn = (c & 15) << 3;
        cpa16(Bd + br * LDB + bn, Bg + (size_t)br * N + bn);
    }
    asm volatile("cp.async.commit_group;\n" ::: "memory");
}

__device__ __forceinline__ void mainloop_h(
    const __half* __restrict__ A, const __half* __restrict__ B,
    int K, int N, int m0, int n0, float (&acc)[4][4][4],
    __half* As, __half* Bs)
{
    const int tid = threadIdx.x, lane = tid & 31, warp = tid >> 5;
    const int wm = (warp & 1) * 64, wn = (warp >> 1) * 32;
    const int KT = K >> 5;
    const int lrow = lane & 15, lsel = (lane >> 4) << 3;

    stage_h(A + (size_t)m0 * K, B + n0, K, N, As, Bs, tid);

    for (int kt = 0; kt < KT; ++kt) {
        int buf = kt & 1;
        if (kt + 1 < KT) {
            stage_h(A + (size_t)m0 * K + (kt + 1) * 32,
                    B + (size_t)(kt + 1) * 32 * N + n0, K, N,
                    As + (buf ^ 1) * AS_SZ, Bs + (buf ^ 1) * BS_SZ, tid);
            asm volatile("cp.async.wait_group 1;\n" ::: "memory");
        } else {
            asm volatile("cp.async.wait_group 0;\n" ::: "memory");
        }
        __syncthreads();
        const __half* Ad = As + buf * AS_SZ;
        const __half* Bd = Bs + buf * BS_SZ;
        #pragma unroll
        for (int kk = 0; kk < 2; ++kk) {
            int kb = kk * 16;
            uint32_t af[4][4], bf[2][4];
            #pragma unroll
            for (int mi = 0; mi < 4; ++mi)
                ldsm4(af[mi][0], af[mi][1], af[mi][2], af[mi][3],
                      sptr(Ad + (wm + mi * 16 + lrow) * LDA + kb + lsel));
            #pragma unroll
            for (int p = 0; p < 2; ++p)
                ldsm4t(bf[p][0], bf[p][1], bf[p][2], bf[p][3],
                       sptr(Bd + (kb + lrow) * LDB + wn + p * 16 + lsel));
            #pragma unroll
            for (int mi = 0; mi < 4; ++mi)
                #pragma unroll
                for (int ni = 0; ni < 4; ++ni)
                    mmaf16(acc[mi][ni][0], acc[mi][ni][1], acc[mi][ni][2], acc[mi][ni][3],
                           af[mi][0], af[mi][1], af[mi][2], af[mi][3],
                           bf[ni >> 1][(ni & 1) * 2], bf[ni >> 1][(ni & 1) * 2 + 1]);
        }
        __syncthreads();
    }
}

// ---------------- QKV: Xh @ W -> scatter half [s,b,h,t,d] --------------------
__global__ __launch_bounds__(256)
void qkv_mma()
{
    __shared__ __half As[2 * AS_SZ];
    __shared__ __half Bs[2 * BS_SZ];
    int z = blockIdx.z; int s = z / 3, p = z - 3 * s;
    const __half* A = g_Xh + (size_t)s * MROWS * EMB;
    const __half* W = (p == 0 ? g_Wqh : (p == 1 ? g_Wkh : g_Wvh)) + (size_t)s * EMB * EMB;
    __half* O = (p == 0 ? g_Q : (p == 1 ? g_K : g_V));
    int m0 = blockIdx.y * 128, n0 = blockIdx.x * 128;

    float acc[4][4][4] = {};
    mainloop_h(A, W, EMB, EMB, m0, n0, acc, As, Bs);

    const int lane = threadIdx.x & 31, warp = threadIdx.x >> 5;
    const int wm = (warp & 1) * 64, wn = (warp >> 1) * 32;
    const int gg = lane >> 2, rr = lane & 3;
    #pragma unroll
    for (int mi = 0; mi < 4; ++mi) {
        int r0 = m0 + wm + mi * 16 + gg;
        #pragma unroll
        for (int ni = 0; ni < 4; ++ni) {
            int c = n0 + wn + ni * 8 + rr * 2;
            int hh = c >> 6, d = c & 63;
            #pragma unroll
            for (int hr = 0; hr < 2; ++hr) {
                int rw = r0 + hr * 8;
                int b = rw >> 9, t = rw & 511;
                size_t dst = ((((size_t)s * 4 + b) * 8 + hh) * 512 + t) * 64 + d;
                __half2 hv = __floats2half2_rn(acc[mi][ni][hr * 2], acc[mi][ni][hr * 2 + 1]);
                *(__half2*)(O + dst) = hv;
            }
        }
    }
}

// ---------------- GEMM + bias + resid -> fp32 ---------------------------------
__global__ __launch_bounds__(256)
void gemm_bias_resid(const __half* __restrict__ Ab, const __half* __restrict__ Bb,
                     const float* __restrict__ biasb, R4 resid,
                     float* __restrict__ Cb, int M, int N, int K)
{
    __shared__ __half As[2 * AS_SZ];
    __shared__ __half Bs[2 * BS_SZ];
    int s = blockIdx.z;
    const __half* A = Ab + (size_t)s * M * K;
    const __half* B = Bb + (size_t)s * K * N;
    const float* bias = biasb + (size_t)s * N;
    const float* R = resid.p[s];
    float* C = Cb + (size_t)s * M * N;
    int m0 = blockIdx.y * 128, n0 = blockIdx.x * 128;

    float acc[4][4][4] = {};
    mainloop_h(A, B, K, N, m0, n0, acc, As, Bs);

    const int lane = threadIdx.x & 31, warp = threadIdx.x >> 5;
    const int wm = (warp & 1) * 64, wn = (warp >> 1) * 32;
    const int gg = lane >> 2, rr = lane & 3;
    #pragma unroll
    for (int mi = 0; mi < 4; ++mi) {
        int r0 = m0 + wm + mi * 16 + gg;
        #pragma unroll
        for (int ni = 0; ni < 4; ++ni) {
            int c = n0 + wn + ni * 8 + rr * 2;
            float bx = bias[c], by = bias[c + 1];
            #pragma unroll
            for (int hr = 0; hr < 2; ++hr) {
                int rw = r0 + hr * 8;
                float2 rv = *(const float2*)(R + (size_t)rw * N + c);
                float v0 = acc[mi][ni][hr * 2 + 0] + bx + rv.x;
                float v1 = acc[mi][ni][hr * 2 + 1] + by + rv.y;
                *(float2*)(C + (size_t)rw * N + c) = make_float2(v0, v1);
            }
        }
    }
}

// ---------------- GEMM + bias + gelu -> fp16 ----------------------------------
__global__ __launch_bounds__(256)
void gemm_bias_gelu(const __half* __restrict__ Ab, const __half* __restrict__ Bb,
                    const float* __restrict__ biasb, __half* __restrict__ Cb,
                    int M, int N, int K)
{
    __shared__ __half As[2 * AS_SZ];
    __shared__ __half Bs[2 * BS_SZ];
    int s = blockIdx.z;
    const __half* A = Ab + (size_t)s * M * K;
    const __half* B = Bb + (size_t)s * K * N;
    const float* bias = biasb + (size_t)s * N;
    __half* C = Cb + (size_t)s * M * N;
    int m0 = blockIdx.y * 128, n0 = blockIdx.x * 128;

    float acc[4][4][4] = {};
    mainloop_h(A, B, K, N, m0, n0, acc, As, Bs);

    const int lane = threadIdx.x & 31, warp = threadIdx.x >> 5;
    const int wm = (warp & 1) * 64, wn = (warp >> 1) * 32;
    const int gg = lane >> 2, rr = lane & 3;
    #pragma unroll
    for (int mi = 0; mi < 4; ++mi) {
        int r0 = m0 + wm + mi * 16 + gg;
        #pragma unroll
        for (int ni = 0; ni < 4; ++ni) {
            int c = n0 + wn + ni * 8 + rr * 2;
            float bx = bias[c], by = bias[c + 1];
            #pragma unroll
            for (int hr = 0; hr < 2; ++hr) {
                int rw = r0 + hr * 8;
                float v0 = gelu_exact(acc[mi][ni][hr * 2 + 0] + bx);
                float v1 = gelu_exact(acc[mi][ni][hr * 2 + 1] + by);
                *(__half2*)(C + (size_t)rw * N + c) = __floats2half2_rn(v0, v1);
            }
        }
    }
}

// ---------------- cross-stream flash attention (fp16 mma) ---------------------
// block: (qt: 64 q rows, h, i*4+b); 128 threads = 4 warps x 16 q rows.
__global__ __launch_bounds__(128)
void attn_h(const float* __restrict__ inter)
{
    __shared__ __half Qs[64 * 72];
    __shared__ __half Ks[64 * 72];
    __shared__ __half Vs[64 * 72];

    const int tid = threadIdx.x, lane = tid & 31, warp = tid >> 5;
    const int qt = blockIdx.x, h = blockIdx.y, ib = blockIdx.z;
    const int i = ib >> 2, b = ib & 3;
    const int gg = lane >> 2, rr = lane & 3;
    const int lrow = lane & 15, lsel = (lane >> 4) << 3;

    const __half* Qg = g_Q + ((((size_t)i * 4 + b) * 8 + h) * 512 + qt * 64) * 64;
    #pragma unroll
    for (int it = 0; it < 4; ++it) {
        int c = tid + it * 128;
        int q = c >> 3, d8 = (c & 7) << 3;
        cpa16(Qs + q * 72 + d8, Qg + q * 64 + d8);
    }
    asm volatile("cp.async.commit_group;\ncp.async.wait_group 0;\n" ::: "memory");
    __syncthreads();

    uint32_t qf[4][4];
    #pragma unroll
    for (int kf = 0; kf < 4; ++kf)
        ldsm4(qf[kf][0], qf[kf][1], qf[kf][2], qf[kf][3],
              sptr(Qs + (warp * 16 + lrow) * 72 + kf * 16 + lsel));

    float Of[8][4] = {};
    for (int j = 0; j < 4; ++j) {
        float coef = 0.125f * __ldg(inter + i * 4 + j);
        const __half* Kg = g_K + (((size_t)j * 4 + b) * 8 + h) * 512 * 64;
        const __half* Vg = g_V + (((size_t)j * 4 + b) * 8 + h) * 512 * 64;
        float m0v = -1e30f, m1v = -1e30f, l0 = 0.f, l1 = 0.f;
        float Oj[8][4] = {};

        for (int kt = 0; kt < 8; ++kt) {
            __syncthreads();
            #pragma unroll
            for (int it = 0; it < 4; ++it) {
                int c = tid + it * 128;
                int r = c >> 3, d8 = (c & 7) << 3;
                cpa16(Ks + r * 72 + d8, Kg + (size_t)(kt * 64 + r) * 64 + d8);
                cpa16(Vs + r * 72 + d8, Vg + (size_t)(kt * 64 + r) * 64 + d8);
            }
            asm volatile("cp.async.commit_group;\ncp.async.wait_group 0;\n" ::: "memory");
            __syncthreads();

            // S = Q K^T : per nf (8 keys), b-frags from K rows (k=d contiguous)
            float S[8][4] = {};
            #pragma unroll
            for (int nf = 0; nf < 8; ++nf) {
                uint32_t kb[2][4];
                #pragma unroll
                for (int p = 0; p < 2; ++p)
                    ldsm4(kb[p][0], kb[p][1], kb[p][2], kb[p][3],
                          sptr(Ks + (nf * 8 + (lane & 7)) * 72 + p * 32 + ((lane >> 3) << 3)));
                #pragma unroll
                for (int kf = 0; kf < 4; ++kf)
                    mmaf16(S[nf][0], S[nf][1], S[nf][2], S[nf][3],
                           qf[kf][0], qf[kf][1], qf[kf][2], qf[kf][3],
                           kb[kf >> 1][(kf & 1) * 2], kb[kf >> 1][(kf & 1) * 2 + 1]);
            }

            // online softmax (rows gg -> c0/c1 use m0v, rows gg+8 -> c2/c3 use m1v)
            float mxA = -1e30f, mxB = -1e30f;
            #pragma unroll
            for (int nf = 0; nf < 8; ++nf) {
                S[nf][0] *= coef; S[nf][1] *= coef;
                S[nf][2] *= coef; S[nf][3] *= coef;
                mxA = fmaxf(mxA, fmaxf(S[nf][0], S[nf][1]));
                mxB = fmaxf(mxB, fmaxf(S[nf][2], S[nf][3]));
            }
            mxA = fmaxf(mxA, __shfl_xor_sync(0xffffffffu, mxA, 1));
            mxA = fmaxf(mxA, __shfl_xor_sync(0xffffffffu, mxA, 2));
            mxB = fmaxf(mxB, __shfl_xor_sync(0xffffffffu, mxB, 1));
            mxB = fmaxf(mxB, __shfl_xor_sync(0xffffffffu, mxB, 2));
            float nm0 = fmaxf(m0v, mxA), nm1 = fmaxf(m1v, mxB);
            float al0 = __expf(m0v - nm0), al1 = __expf(m1v - nm1);

            uint32_t pf[4][4];
            float rs0 = 0.f, rs1 = 0.f;
            #pragma unroll
            for (int nf = 0; nf < 8; ++nf) {
                float p0 = __expf(S[nf][0] - nm0), p1 = __expf(S[nf][1] - nm0);
                float p2 = __expf(S[nf][2] - nm1), p3 = __expf(S[nf][3] - nm1);
                rs0 += p0 + p1; rs1 += p2 + p3;
                int kf = nf >> 1;
                if ((nf & 1) == 0) { pf[kf][0] = packh2(p0, p1); pf[kf][1] = packh2(p2, p3); }
                else               { pf[kf][2] = packh2(p0, p1); pf[kf][3] = packh2(p2, p3); }
            }
            rs0 += __shfl_xor_sync(0xffffffffu, rs0, 1);
            rs0 += __shfl_xor_sync(0xffffffffu, rs0, 2);
            rs1 += __shfl_xor_sync(0xffffffffu, rs1, 1);
            rs1 += __shfl_xor_sync(0xffffffffu, rs1, 2);
            l0 = l0 * al0 + rs0; l1 = l1 * al1 + rs1;
            m0v = nm0; m1v = nm1;
            #pragma unroll
            for (int nf = 0; nf < 8; ++nf) {
                Oj[nf][0] *= al0; Oj[nf][1] *= al0;
                Oj[nf][2] *= al1; Oj[nf][3] *= al1;
            }

            // Oj += P @ V  (V b-frags via ldmatrix.trans)
            #pragma unroll
            for (int kf = 0; kf < 4; ++kf) {
                #pragma unroll
                for (int p = 0; p < 4; ++p) {
                    uint32_t vb[4];
                    ldsm4t(vb[0], vb[1], vb[2], vb[3],
                           sptr(Vs + (kf * 16 + lrow) * 72 + p * 16 + lsel));
                    mmaf16(Oj[2 * p][0], Oj[2 * p][1], Oj[2 * p][2], Oj[2 * p][3],
                           pf[kf][0], pf[kf][1], pf[kf][2], pf[kf][3], vb[0], vb[1]);
                    mmaf16(Oj[2 * p + 1][0], Oj[2 * p + 1][1], Oj[2 * p + 1][2], Oj[2 * p + 1][3],
                           pf[kf][0], pf[kf][1], pf[kf][2], pf[kf][3], vb[2], vb[3]);
                }
            }
        }
        float inv0 = 1.f / l0, inv1 = 1.f / l1;
        #pragma unroll
        for (int nf = 0; nf < 8; ++nf) {
            Of[nf][0] += Oj[nf][0] * inv0; Of[nf][1] += Oj[nf][1] * inv0;
            Of[nf][2] += Oj[nf][2] * inv1; Of[nf][3] += Oj[nf][3] * inv1;
        }
    }

    // transpose via smem (reuse Qs), store half to g_MH[i,b, h*64+d, q]
    __syncthreads();
    #pragma unroll
    for (int nf = 0; nf < 8; ++nf) {
        int col = nf * 8 + rr * 2;
        int lq = warp * 16 + gg;
        Qs[col * 72 + lq]           = __float2half(Of[nf][0] * 0.25f);
        Qs[(col + 1) * 72 + lq]     = __float2half(Of[nf][1] * 0.25f);
        Qs[col * 72 + lq + 8]       = __float2half(Of[nf][2] * 0.25f);
        Qs[(col + 1) * 72 + lq + 8] = __float2half(Of[nf][3] * 0.25f);
    }
    __syncthreads();
    __half* Og = g_MH + (((size_t)i * 4 + b) * 512 + h * 64) * 512 + qt * 64;
    #pragma unroll
    for (int it = 0; it < 4; ++it) {
        int c = tid + it * 128;
        int d = c >> 3, q8 = (c & 7) << 3;
        *(uint4*)(Og + (size_t)d * 512 + q8) = *(const uint4*)(Qs + d * 72 + q8);
    }
}

// ---------------- row LayerNorm over E=512 (fp32 in, fp32 + optional fp16 out)
__global__ __launch_bounds__(128)
void ln_kernel(const float* __restrict__ in, const float* __restrict__ gw,
               const float* __restrict__ bw, float* __restrict__ out,
               __half* __restrict__ outh)
{
    int row = blockIdx.x;
    int s = row >> 11;
    int t = threadIdx.x;

    float4 xv = ((const float4*)(in + (size_t)row * 512))[t];
    float sum = xv.x + xv.y + xv.z + xv.w;
    float sq  = xv.x * xv.x + xv.y * xv.y + xv.z * xv.z + xv.w * xv.w;
    #pragma unroll
    for (int off = 16; off >= 1; off >>= 1) {
        sum += __shfl_xor_sync(0xffffffffu, sum, off);
        sq  += __shfl_xor_sync(0xffffffffu, sq,  off);
    }
    __shared__ float s_sum[4], s_sq[4];
    int w = t >> 5, lane = t & 31;
    if (lane == 0) { s_sum[w] = sum; s_sq[w] = sq; }
    __syncthreads();
    sum = s_sum[0] + s_sum[1] + s_sum[2] + s_sum[3];
    sq  = s_sq[0]  + s_sq[1]  + s_sq[2]  + s_sq[3];

    float mean = sum * (1.0f / 512.0f);
    float var  = sq  * (1.0f / 512.0f) - mean * mean;
    float inv  = rsqrtf(var + 1e-5f);

    float4 g4 = ((const float4*)(gw + s * 512))[t];
    float4 b4 = ((const float4*)(bw + s * 512))[t];
    float4 o;
    o.x = (xv.x - mean) * inv * g4.x + b4.x;
    o.y = (xv.y - mean) * inv * g4.y + b4.y;
    o.z = (xv.z - mean) * inv * g4.z + b4.z;
    o.w = (xv.w - mean) * inv * g4.w + b4.w;
    ((float4*)(out + (size_t)row * 512))[t] = o;
    if (outh) {
        __half2 h0 = __floats2half2_rn(o.x, o.y);
        __half2 h1 = __floats2half2_rn(o.z, o.w);
        ((__half2*)(outh + (size_t)row * 512))[t * 2]     = h0;
        ((__half2*)(outh + (size_t)row * 512))[t * 2 + 1] = h1;
    }
}

// ---------------- launch -----------------------------------------------------
extern "C" void kernel_launch(void* const* d_in, const int* in_sizes, int n_in,
                              void* d_out, int out_size)
{
    const float* xs0 = (const float*)d_in[0];
    const float* xs1 = (const float*)d_in[1];
    const float* xs2 = (const float*)d_in[2];
    const float* xs3 = (const float*)d_in[3];
    const float* Wq  = (const float*)d_in[4];
    const float* Wk  = (const float*)d_in[5];
    const float* Wv  = (const float*)d_in[6];
    const float* Wo  = (const float*)d_in[7];
    const float* bo  = (const float*)d_in[8];
    const float* ln1g = (const float*)d_in[9];
    const float* ln1b = (const float*)d_in[10];
    const float* ln2g = (const float*)d_in[11];
    const float* ln2b = (const float*)d_in[12];
    const float* W1  = (const float*)d_in[13];
    const float* bf1 = (const float*)d_in[14];
    const float* W2  = (const float*)d_in[15];
    const float* bf2 = (const float*)d_in[16];
    const float* inter = (const float*)d_in[17];

    __half *wq, *wk, *wv, *wo, *w1, *w2, *mh, *hb, *r1h;
    float *t1, *r1, *t2;
    cudaGetSymbolAddress((void**)&wq, g_Wqh);
    cudaGetSymbolAddress((void**)&wk, g_Wkh);
    cudaGetSymbolAddress((void**)&wv, g_Wvh);
    cudaGetSymbolAddress((void**)&wo, g_Woh);
    cudaGetSymbolAddress((void**)&w1, g_W1h);
    cudaGetSymbolAddress((void**)&w2, g_W2h);
    cudaGetSymbolAddress((void**)&mh, g_MH);
    cudaGetSymbolAddress((void**)&hb, g_HB);
    cudaGetSymbolAddress((void**)&r1h, g_R1h);
    cudaGetSymbolAddress((void**)&t1, g_T1);
    cudaGetSymbolAddress((void**)&r1, g_R1);
    cudaGetSymbolAddress((void**)&t2, g_T2);

    const int NW = 4 * 512 * 512;   // elems per small weight set
    const int NF = 4 * 512 * 2048;
    cvt_kernel<<<NW / 1024, 256>>>(Wq, wq);
    cvt_kernel<<<NW / 1024, 256>>>(Wk, wk);
    cvt_kernel<<<NW / 1024, 256>>>(Wv, wv);
    cvt_kernel<<<NW / 1024, 256>>>(Wo, wo);
    cvt_kernel<<<NF / 1024, 256>>>(W1, w1);
    cvt_kernel<<<NF / 1024, 256>>>(W2, w2);
    xcvt_kernel<<<dim3(1024, 4), 256>>>(xs0, xs1, xs2, xs3);

    // QKV projections (fp16 in/out)
    qkv_mma<<<dim3(4, 16, 12), 256>>>();

    // cross-stream attention
    attn_h<<<dim3(8, 8, 16), 128>>>(inter);

    // T1 = MH @ Wo + bo + x   (resid read directly from inputs)
    R4 rx; rx.p[0] = xs0; rx.p[1] = xs1; rx.p[2] = xs2; rx.p[3] = xs3;
    gemm_bias_resid<<<dim3(4, 16, 4), 256>>>(mh, wo, bo, rx, t1, MROWS, EMB, EMB);

    // R1 = LN1(T1)  (fp32 + fp16 copies)
    ln_kernel<<<8192, 128>>>(t1, ln1g, ln1b, r1, r1h);

    // HB = gelu(R1h @ W1 + bf1)  (fp16 out)
    gemm_bias_gelu<<<dim3(16, 16, 4), 256>>>(r1h, w1, bf1, hb, MROWS, 4 * EMB, EMB);

    // T2 = HB @ W2 + bf2 + R1
    R4 rr; for (int s = 0; s < 4; ++s) rr.p[s] = r1 + (size_t)s * MROWS * EMB;
    gemm_bias_resid<<<dim3(4, 16, 4), 256>>>(hb, w2, bf2, rr, t2, MROWS, EMB, 2048);

    // out = LN2(T2)
    ln_kernel<<<8192, 128>>>(t2, ln2g, ln2b, (float*)d_out, nullptr);
}